// round 11
// baseline (speedup 1.0000x reference)
#include <cuda_runtime.h>

#define NN 50000
#define EE 800000
#define HH 128
#define DD 3
#define EM 128     // rows (edges/nodes) per block
#define SA1 132    // layer-1 A stride in u32 (bf16x2 pairs)
#define SM1 68     // M buffers stride in u32

// ---------------- device scratch ----------------
__device__ __align__(16) float g_agg[NN * HH];
__device__ __align__(16) float g_coordcnt[NN * 4];   // {cx, cy, cz, cnt}
// fragment-prepacked bf16 weights: [chunk][p=0..7][lane=0..31] uint4
__device__ __align__(16) uint4 g_ew1f[16 * 256];   // K=256
__device__ __align__(16) uint4 g_ew2f[8 * 256];    // K=128
__device__ __align__(16) uint4 g_cw1f[8 * 256];    // K=128
__device__ __align__(16) uint4 g_nw1f[16 * 256];   // K=256
__device__ __align__(16) uint4 g_nw2f[8 * 256];    // K=128

__device__ __forceinline__ float silu_f(float v) { return v / (1.0f + __expf(-v)); }
__device__ __forceinline__ float sigmoid_f(float v) { return 1.0f / (1.0f + __expf(-v)); }

__device__ __forceinline__ unsigned pack_bf2(float lo, float hi) {
    unsigned d; asm("cvt.rn.bf16x2.f32 %0, %1, %2;" : "=r"(d) : "f"(hi), "f"(lo));
    return d;
}
__device__ __forceinline__ float bf_lo(unsigned u) { return __uint_as_float(u << 16); }
__device__ __forceinline__ float bf_hi(unsigned u) { return __uint_as_float(u & 0xffff0000u); }

__device__ __forceinline__ void mma_bf16(float c[4],
    unsigned a0, unsigned a1, unsigned a2, unsigned a3,
    unsigned b0, unsigned b1)
{
    asm volatile("mma.sync.aligned.m16n8k16.row.col.f32.bf16.bf16.f32 "
        "{%0,%1,%2,%3}, {%4,%5,%6,%7}, {%8,%9}, {%0,%1,%2,%3};\n"
        : "+f"(c[0]), "+f"(c[1]), "+f"(c[2]), "+f"(c[3])
        : "r"(a0), "r"(a1), "r"(a2), "r"(a3), "r"(b0), "r"(b1));
}
__device__ __forceinline__ void red_add_v4(float* p, float a, float b, float c, float d) {
    asm volatile("red.global.add.v4.f32 [%0], {%1,%2,%3,%4};"
                 :: "l"(p), "f"(a), "f"(b), "f"(c), "f"(d) : "memory");
}

__global__ void zero_kernel() {
    const int total = NN * HH + NN * 4;
    for (int i = blockIdx.x * blockDim.x + threadIdx.x; i < total;
         i += gridDim.x * blockDim.x) {
        if (i < NN * HH) g_agg[i] = 0.0f;
        else g_coordcnt[i - NN * HH] = 0.0f;
    }
}

// Pack weights into bf16 mma fragment order (layout unchanged from round 8).
__global__ void prep_kernel(const float* __restrict__ EW1, const float* __restrict__ EW2,
                            const float* __restrict__ CW1, const float* __restrict__ NW1,
                            const float* __restrict__ NW2) {
    const int idx = blockIdx.x * blockDim.x + threadIdx.x;
    if (idx >= 56 * 256) return;
    const int chunk = idx >> 8;
    const int rem = idx & 255;
    const int p = rem >> 5, lane = rem & 31;
    const int t = lane & 3, g = lane >> 2;

    const float* W; uint4* dst; int kbase; int loc;
    if (chunk < 16)      { W = EW1; dst = g_ew1f; loc = chunk;      kbase = loc * 16; }
    else if (chunk < 24) { W = EW2; dst = g_ew2f; loc = chunk - 16; kbase = loc * 16; }
    else if (chunk < 32) { W = CW1; dst = g_cw1f; loc = chunk - 24; kbase = loc * 16; }
    else if (chunk < 48) { W = NW1; dst = g_nw1f; loc = chunk - 32; kbase = loc * 16; }
    else                 { W = NW2; dst = g_nw2f; loc = chunk - 48; kbase = loc * 16; }

    const int c0 = p * 16 + g;
    const int c1 = c0 + 8;
    const int k0 = kbase + 2 * t;
    uint4 v;
    v.x = pack_bf2(W[k0 * HH + c0],       W[(k0 + 1) * HH + c0]);
    v.y = pack_bf2(W[(k0 + 8) * HH + c0], W[(k0 + 9) * HH + c0]);
    v.z = pack_bf2(W[k0 * HH + c1],       W[(k0 + 1) * HH + c1]);
    v.w = pack_bf2(W[(k0 + 8) * HH + c1], W[(k0 + 9) * HH + c1]);
    dst[loc * 256 + p * 32 + lane] = v;
}

// bf16 GEMM, 64x64 warp tile: acc[32][4] += A[warp 64 rows, K] @ W[K, warp 64 cols]
// B fragments software-pipelined (next chunk loaded before current chunk's MMAs).
__device__ __forceinline__ void gemm_bf64(
    const uint4* __restrict__ Wf, int nchunks,
    const unsigned* A32, int sa,
    float acc[32][4], int wm, int wn, int g, int t, int lane)
{
    const unsigned* arow = A32 + (wm * 64 + g) * sa + t;
    const uint4* wc = Wf + wn * 128 + lane;
    uint4 nf0 = wc[0], nf1 = wc[32], nf2 = wc[64], nf3 = wc[96];
    for (int kk = 0; kk < nchunks; ++kk) {
        const int ka = kk * 8;
        const uint4 f0 = nf0, f1 = nf1, f2 = nf2, f3 = nf3;
        if (kk + 1 < nchunks) {
            const uint4* wnx = wc + (kk + 1) * 256;
            nf0 = wnx[0]; nf1 = wnx[32]; nf2 = wnx[64]; nf3 = wnx[96];
        }
        unsigned a[4][4];
        #pragma unroll
        for (int mi = 0; mi < 4; ++mi) {
            const unsigned* ar = arow + mi * 16 * sa;
            a[mi][0] = ar[ka];
            a[mi][1] = ar[8 * sa + ka];
            a[mi][2] = ar[ka + 4];
            a[mi][3] = ar[8 * sa + ka + 4];
        }
        #pragma unroll
        for (int mi = 0; mi < 4; ++mi) {
            float (*ac)[4] = &acc[mi * 8];
            mma_bf16(ac[0], a[mi][0], a[mi][1], a[mi][2], a[mi][3], f0.x, f0.y);
            mma_bf16(ac[1], a[mi][0], a[mi][1], a[mi][2], a[mi][3], f0.z, f0.w);
            mma_bf16(ac[2], a[mi][0], a[mi][1], a[mi][2], a[mi][3], f1.x, f1.y);
            mma_bf16(ac[3], a[mi][0], a[mi][1], a[mi][2], a[mi][3], f1.z, f1.w);
            mma_bf16(ac[4], a[mi][0], a[mi][1], a[mi][2], a[mi][3], f2.x, f2.y);
            mma_bf16(ac[5], a[mi][0], a[mi][1], a[mi][2], a[mi][3], f2.z, f2.w);
            mma_bf16(ac[6], a[mi][0], a[mi][1], a[mi][2], a[mi][3], f3.x, f3.y);
            mma_bf16(ac[7], a[mi][0], a[mi][1], a[mi][2], a[mi][3], f3.z, f3.w);
        }
    }
}

__device__ __forceinline__ void acc_zero(float acc[32][4]) {
    #pragma unroll
    for (int i = 0; i < 32; ++i)
        #pragma unroll
        for (int j = 0; j < 4; ++j) acc[i][j] = 0.f;
}

// epilogue: silu(acc + bias) -> packed bf16x2 smem
__device__ __forceinline__ void epi_silu_bf(
    float acc[32][4], unsigned* Out32, int s32, const float* bias,
    int wm, int wn, int g, int t)
{
    #pragma unroll
    for (int mi = 0; mi < 4; ++mi) {
        const int r0 = wm * 64 + mi * 16 + g;
        #pragma unroll
        for (int n8 = 0; n8 < 8; ++n8) {
            const int c = wn * 64 + n8 * 8 + 2 * t;
            const float b0 = bias[c], b1 = bias[c + 1];
            const float* a = acc[mi * 8 + n8];
            Out32[r0 * s32 + (c >> 1)] =
                pack_bf2(silu_f(a[0] + b0), silu_f(a[1] + b1));
            Out32[(r0 + 8) * s32 + (c >> 1)] =
                pack_bf2(silu_f(a[2] + b0), silu_f(a[3] + b1));
        }
    }
}

// ---------------- fused edge kernel ----------------
__global__ __launch_bounds__(128, 2) void edge_kernel(
    const float* __restrict__ h, const float* __restrict__ x,
    const int* __restrict__ ei, const float* __restrict__ eattr,
    const float* __restrict__ EW1,
    const float* __restrict__ eb1, const float* __restrict__ eb2,
    const float* __restrict__ cb1, const float* __restrict__ CW2,
    const float* __restrict__ AW, const float* __restrict__ ab)
{
    extern __shared__ unsigned dsm[];
    unsigned* A1 = dsm;                 // [128][132] u32
    unsigned* Mm = dsm;                 // [128][68] alias (A1 dead after GEMM1)
    unsigned* M1 = dsm + EM * SA1;      // [128][68]
    unsigned* P  = M1;

    __shared__ int   s_row[EM];
    __shared__ float s_cd[EM][3];
    __shared__ float s_rad[EM], s_ea[EM], s_att[EM];
    __shared__ float s_b1[HH], s_b2[HH], s_bc[HH], s_aw[HH], s_c2[HH];
    __shared__ float s_wr[HH], s_we[HH];

    const int tid  = threadIdx.x;
    const int lane = tid & 31, warp = tid >> 5;
    const int g = lane >> 2, t = lane & 3;
    const int wm = warp & 1, wn = warp >> 1;
    const int e0 = blockIdx.x * EM;

    if (tid < HH) {
        s_b1[tid] = eb1[tid]; s_b2[tid] = eb2[tid]; s_bc[tid] = cb1[tid];
        s_aw[tid] = AW[tid];  s_c2[tid] = CW2[tid];
        s_wr[tid] = EW1[256 * HH + tid];
        s_we[tid] = EW1[257 * HH + tid];
    }
    {   // geometry: 1 thread per edge (tid covers all 128 edges)
        const int e = tid;
        const int idx = e0 + e;
        const int r = ei[idx], c = ei[EE + idx];
        s_row[e] = r;
        float rad = 0.f;
        #pragma unroll
        for (int d = 0; d < 3; ++d) {
            const float df = x[r * 3 + d] - x[c * 3 + d];
            s_cd[e][d] = df; rad += df * df;
        }
        s_rad[e] = rad;
        s_ea[e] = eattr[idx];
    }
    // gather h[row], h[col], pack bf16x2 (4 warps: e = p*4 + warp)
    #pragma unroll
    for (int p = 0; p < 32; ++p) {
        const int e = p * 4 + warp;
        const int idx = e0 + e;
        const int r = ei[idx], c = ei[EE + idx];
        const float4 vr = *(const float4*)&h[r * HH + lane * 4];
        const float4 vc = *(const float4*)&h[c * HH + lane * 4];
        uint2 ur, uc;
        ur.x = pack_bf2(vr.x, vr.y); ur.y = pack_bf2(vr.z, vr.w);
        uc.x = pack_bf2(vc.x, vc.y); uc.y = pack_bf2(vc.z, vc.w);
        *(uint2*)&A1[e * SA1 + lane * 2]      = ur;
        *(uint2*)&A1[e * SA1 + 64 + lane * 2] = uc;
    }
    __syncthreads();

    float acc[32][4];

    // ---- layer 1: K=256 bf16 + fp32 rank-2 tail ----
    acc_zero(acc);
    gemm_bf64(g_ew1f, 16, A1, SA1, acc, wm, wn, g, t, lane);
    #pragma unroll
    for (int mi = 0; mi < 4; ++mi) {
        const int r = wm * 64 + mi * 16 + g;
        const float r0 = s_rad[r], r1 = s_rad[r + 8];
        const float e0f = s_ea[r], e1f = s_ea[r + 8];
        #pragma unroll
        for (int n8 = 0; n8 < 8; ++n8) {
            const int c = wn * 64 + n8 * 8 + 2 * t;
            float* a = acc[mi * 8 + n8];
            a[0] += r0 * s_wr[c]     + e0f * s_we[c];
            a[1] += r0 * s_wr[c + 1] + e0f * s_we[c + 1];
            a[2] += r1 * s_wr[c]     + e1f * s_we[c];
            a[3] += r1 * s_wr[c + 1] + e1f * s_we[c + 1];
        }
    }
    epi_silu_bf(acc, M1, SM1, s_b1, wm, wn, g, t);
    __syncthreads();

    // ---- layer 2: K=128 ----
    acc_zero(acc);
    gemm_bf64(g_ew2f, 8, M1, SM1, acc, wm, wn, g, t, lane);
    epi_silu_bf(acc, Mm, SM1, s_b2, wm, wn, g, t);   // Mm aliases dead A1
    __syncthreads();

    // ---- attention gate: 4 threads per edge, 4 passes ----
    #pragma unroll
    for (int pass = 0; pass < 4; ++pass) {
        const int e = (tid >> 2) + pass * 32, q = tid & 3;
        const unsigned* mrow = Mm + e * SM1 + q * 16;
        const float* aw = s_aw + q * 32;
        float s = 0.f;
        #pragma unroll
        for (int k = 0; k < 16; ++k) {
            const unsigned u = mrow[k];
            s += bf_lo(u) * aw[2 * k] + bf_hi(u) * aw[2 * k + 1];
        }
        s += __shfl_down_sync(0xffffffffu, s, 1);
        s += __shfl_down_sync(0xffffffffu, s, 2);
        if (q == 0) s_att[e] = sigmoid_f(s + ab[0]);
    }
    __syncthreads();

    // ---- gate + vectorized scatter ----
    #pragma unroll
    for (int p = 0; p < 32; ++p) {
        const int q = p * 128 + tid;
        const int e = q >> 5, j = q & 31;
        unsigned* base = Mm + e * SM1 + 2 * j;
        const float a = s_att[e];
        const unsigned u0 = base[0], u1 = base[1];
        const float f0 = bf_lo(u0) * a, f1 = bf_hi(u0) * a;
        const float f2 = bf_lo(u1) * a, f3 = bf_hi(u1) * a;
        red_add_v4(&g_agg[s_row[e] * HH + 4 * j], f0, f1, f2, f3);
        base[0] = pack_bf2(f0, f1);
        base[1] = pack_bf2(f2, f3);
    }
    __syncthreads();

    // ---- coord MLP layer: K=128 ----
    acc_zero(acc);
    gemm_bf64(g_cw1f, 8, Mm, SM1, acc, wm, wn, g, t, lane);
    epi_silu_bf(acc, P, SM1, s_bc, wm, wn, g, t);    // P aliases dead M1
    __syncthreads();

    // ---- coord_update + fused coord/count scatter ----
    #pragma unroll
    for (int pass = 0; pass < 4; ++pass) {
        const int e = (tid >> 2) + pass * 32, q = tid & 3;
        const unsigned* prow = P + e * SM1 + q * 16;
        const float* c2 = s_c2 + q * 32;
        float s = 0.f;
        #pragma unroll
        for (int k = 0; k < 16; ++k) {
            const unsigned u = prow[k];
            s += bf_lo(u) * c2[2 * k] + bf_hi(u) * c2[2 * k + 1];
        }
        s += __shfl_down_sync(0xffffffffu, s, 1);
        s += __shfl_down_sync(0xffffffffu, s, 2);
        if (q == 0) {
            const int r = s_row[e];
            red_add_v4(&g_coordcnt[r * 4],
                       s_cd[e][0] * s, s_cd[e][1] * s, s_cd[e][2] * s, 1.0f);
        }
    }
}

// ---------------- node kernel ----------------
__global__ __launch_bounds__(128, 2) void node_kernel(
    const float* __restrict__ h, const float* __restrict__ x,
    const float* __restrict__ nb1, const float* __restrict__ nb2,
    float* __restrict__ out_h, float* __restrict__ out_x)
{
    extern __shared__ unsigned dsm[];
    unsigned* A1 = dsm;                 // [128][132]
    unsigned* M1 = dsm + EM * SA1;      // [128][68]

    __shared__ float s_nb1[HH], s_nb2[HH];

    const int tid  = threadIdx.x;
    const int lane = tid & 31, warp = tid >> 5;
    const int g = lane >> 2, t = lane & 3;
    const int wm = warp & 1, wn = warp >> 1;
    const int n0 = blockIdx.x * EM;

    if (tid < HH) { s_nb1[tid] = nb1[tid]; s_nb2[tid] = nb2[tid]; }
    #pragma unroll
    for (int p = 0; p < 32; ++p) {
        const int n = p * 4 + warp;
        int r = n0 + n; if (r >= NN) r = NN - 1;
        const float4 vh = *(const float4*)&h[r * HH + lane * 4];
        const float4 va = *(const float4*)&g_agg[r * HH + lane * 4];
        uint2 uh, ua;
        uh.x = pack_bf2(vh.x, vh.y); uh.y = pack_bf2(vh.z, vh.w);
        ua.x = pack_bf2(va.x, va.y); ua.y = pack_bf2(va.z, va.w);
        *(uint2*)&A1[n * SA1 + lane * 2]      = uh;
        *(uint2*)&A1[n * SA1 + 64 + lane * 2] = ua;
    }
    __syncthreads();

    float acc[32][4];
    acc_zero(acc);
    gemm_bf64(g_nw1f, 16, A1, SA1, acc, wm, wn, g, t, lane);
    epi_silu_bf(acc, M1, SM1, s_nb1, wm, wn, g, t);
    __syncthreads();

    acc_zero(acc);
    gemm_bf64(g_nw2f, 8, M1, SM1, acc, wm, wn, g, t, lane);

    // residual epilogue straight to gmem (fp32)
    #pragma unroll
    for (int mi = 0; mi < 4; ++mi) {
        const int r0 = n0 + wm * 64 + mi * 16 + g;
        #pragma unroll
        for (int n8 = 0; n8 < 8; ++n8) {
            const int c = wn * 64 + n8 * 8 + 2 * t;
            const float b0 = s_nb2[c], b1 = s_nb2[c + 1];
            const float* a = acc[mi * 8 + n8];
            if (r0 < NN) {
                float2 v;
                v.x = h[r0 * HH + c]     + a[0] + b0;
                v.y = h[r0 * HH + c + 1] + a[1] + b1;
                *(float2*)&out_h[r0 * HH + c] = v;
            }
            if (r0 + 8 < NN) {
                float2 v;
                v.x = h[(r0 + 8) * HH + c]     + a[2] + b0;
                v.y = h[(r0 + 8) * HH + c + 1] + a[3] + b1;
                *(float2*)&out_h[(r0 + 8) * HH + c] = v;
            }
        }
    }

    for (int i = tid; i < EM * DD; i += 128) {
        const int n = i / 3, d = i % 3;
        const int r = n0 + n;
        if (r < NN) {
            float cnt = g_coordcnt[r * 4 + 3];
            cnt = (cnt < 1.0f) ? 1.0f : cnt;
            out_x[r * 3 + d] = x[r * 3 + d] + g_coordcnt[r * 4 + d] / cnt;
        }
    }
}

// ---------------- launch ----------------
extern "C" void kernel_launch(void* const* d_in, const int* in_sizes, int n_in,
                              void* d_out, int out_size) {
    const float* h     = (const float*)d_in[0];
    const float* x     = (const float*)d_in[1];
    const int*   ei    = (const int*)d_in[2];
    const float* eattr = (const float*)d_in[3];
    const float* EW1   = (const float*)d_in[4];
    const float* eb1   = (const float*)d_in[5];
    const float* EW2   = (const float*)d_in[6];
    const float* eb2   = (const float*)d_in[7];
    const float* NW1   = (const float*)d_in[8];
    const float* nb1   = (const float*)d_in[9];
    const float* NW2   = (const float*)d_in[10];
    const float* nb2   = (const float*)d_in[11];
    const float* CW1   = (const float*)d_in[12];
    const float* cb1   = (const float*)d_in[13];
    const float* CW2   = (const float*)d_in[14];
    const float* AW    = (const float*)d_in[15];
    const float* ab    = (const float*)d_in[16];

    float* out_h = (float*)d_out;
    float* out_x = (float*)d_out + (size_t)NN * HH;

    const int smem_bytes = (EM * SA1 + EM * SM1) * 4;   // 102,400 B
    cudaFuncSetAttribute(edge_kernel,
                         cudaFuncAttributeMaxDynamicSharedMemorySize, smem_bytes);
    cudaFuncSetAttribute(node_kernel,
                         cudaFuncAttributeMaxDynamicSharedMemorySize, smem_bytes);

    zero_kernel<<<1024, 256>>>();
    prep_kernel<<<56, 256>>>(EW1, EW2, CW1, NW1, NW2);
    edge_kernel<<<EE / EM, 128, smem_bytes>>>(h, x, ei, eattr, EW1,
                                              eb1, eb2, cb1, CW2, AW, ab);
    node_kernel<<<(NN + EM - 1) / EM, 128, smem_bytes>>>(h, x, nb1, nb2,
                                                         out_h, out_x);
}

// round 13
// speedup vs baseline: 1.0954x; 1.0954x over previous
#include <cuda_runtime.h>

#define NN 50000
#define EE 800000
#define HH 128
#define DD 3
#define EM 64      // rows (edges/nodes) per block
#define SA1 132    // layer-1 A stride in u32 (bf16x2 pairs)
#define SM1 68     // M buffers stride in u32
#define NSTG 5     // cp.async pipeline stages (4KB each)

// ---------------- device scratch ----------------
__device__ __align__(16) float g_agg[NN * HH];
__device__ __align__(16) float g_coordcnt[NN * 4];   // {cx, cy, cz, cnt}
// fragment-prepacked bf16 weights: [chunk][p=0..7][lane=0..31] uint4
__device__ __align__(16) uint4 g_ew1f[16 * 256];   // K=256
__device__ __align__(16) uint4 g_ew2f[8 * 256];    // K=128
__device__ __align__(16) uint4 g_cw1f[8 * 256];    // K=128
__device__ __align__(16) uint4 g_nw1f[16 * 256];   // K=256
__device__ __align__(16) uint4 g_nw2f[8 * 256];    // K=128

__device__ __forceinline__ float silu_f(float v) { return v / (1.0f + __expf(-v)); }
__device__ __forceinline__ float sigmoid_f(float v) { return 1.0f / (1.0f + __expf(-v)); }

__device__ __forceinline__ unsigned pack_bf2(float lo, float hi) {
    unsigned d; asm("cvt.rn.bf16x2.f32 %0, %1, %2;" : "=r"(d) : "f"(hi), "f"(lo));
    return d;
}
__device__ __forceinline__ float bf_lo(unsigned u) { return __uint_as_float(u << 16); }
__device__ __forceinline__ float bf_hi(unsigned u) { return __uint_as_float(u & 0xffff0000u); }

__device__ __forceinline__ void mma_bf16(float c[4],
    unsigned a0, unsigned a1, unsigned a2, unsigned a3,
    unsigned b0, unsigned b1)
{
    asm volatile("mma.sync.aligned.m16n8k16.row.col.f32.bf16.bf16.f32 "
        "{%0,%1,%2,%3}, {%4,%5,%6,%7}, {%8,%9}, {%0,%1,%2,%3};\n"
        : "+f"(c[0]), "+f"(c[1]), "+f"(c[2]), "+f"(c[3])
        : "r"(a0), "r"(a1), "r"(a2), "r"(a3), "r"(b0), "r"(b1));
}
__device__ __forceinline__ void red_add_v4(float* p, float a, float b, float c, float d) {
    asm volatile("red.global.add.v4.f32 [%0], {%1,%2,%3,%4};"
                 :: "l"(p), "f"(a), "f"(b), "f"(c), "f"(d) : "memory");
}

// ---- cp.async helpers ----
__device__ __forceinline__ void cp16(unsigned dst, const void* src) {
    asm volatile("cp.async.cg.shared.global [%0], [%1], 16;" :: "r"(dst), "l"(src));
}
#define CP_COMMIT() asm volatile("cp.async.commit_group;" ::: "memory")
#define CP_WAIT(n)  asm volatile("cp.async.wait_group %0;" :: "n"(n) : "memory")

// stage one 4KB weight chunk (256 uint4) with 128 threads
__device__ __forceinline__ void stage_chunk(uint4* dstv, const uint4* __restrict__ src, int tid) {
    const unsigned d = (unsigned)__cvta_generic_to_shared(dstv) + tid * 16;
    cp16(d, src + tid);
    cp16(d + 2048, src + tid + 128);
}

__global__ void zero_kernel() {
    const int total = NN * HH + NN * 4;
    for (int i = blockIdx.x * blockDim.x + threadIdx.x; i < total;
         i += gridDim.x * blockDim.x) {
        if (i < NN * HH) g_agg[i] = 0.0f;
        else g_coordcnt[i - NN * HH] = 0.0f;
    }
}

// Pack weights into bf16 mma fragment order (layout unchanged from round 8).
__global__ void prep_kernel(const float* __restrict__ EW1, const float* __restrict__ EW2,
                            const float* __restrict__ CW1, const float* __restrict__ NW1,
                            const float* __restrict__ NW2) {
    const int idx = blockIdx.x * blockDim.x + threadIdx.x;
    if (idx >= 56 * 256) return;
    const int chunk = idx >> 8;
    const int rem = idx & 255;
    const int p = rem >> 5, lane = rem & 31;
    const int t = lane & 3, g = lane >> 2;

    const float* W; uint4* dst; int kbase; int loc;
    if (chunk < 16)      { W = EW1; dst = g_ew1f; loc = chunk;      kbase = loc * 16; }
    else if (chunk < 24) { W = EW2; dst = g_ew2f; loc = chunk - 16; kbase = loc * 16; }
    else if (chunk < 32) { W = CW1; dst = g_cw1f; loc = chunk - 24; kbase = loc * 16; }
    else if (chunk < 48) { W = NW1; dst = g_nw1f; loc = chunk - 32; kbase = loc * 16; }
    else                 { W = NW2; dst = g_nw2f; loc = chunk - 48; kbase = loc * 16; }

    const int c0 = p * 16 + g;
    const int c1 = c0 + 8;
    const int k0 = kbase + 2 * t;
    uint4 v;
    v.x = pack_bf2(W[k0 * HH + c0],       W[(k0 + 1) * HH + c0]);
    v.y = pack_bf2(W[(k0 + 8) * HH + c0], W[(k0 + 9) * HH + c0]);
    v.z = pack_bf2(W[k0 * HH + c1],       W[(k0 + 1) * HH + c1]);
    v.w = pack_bf2(W[(k0 + 8) * HH + c1], W[(k0 + 9) * HH + c1]);
    dst[loc * 256 + p * 32 + lane] = v;
}

// bf16 GEMM, 32x64 warp tile, cp.async-pipelined B through smem bstage.
// acc[16][4]: acc[0..7] rows wm*32+g(+8), acc[8..15] rows +16.
// Requires: a __syncthreads() between any prior bstage/A-smem reads|writes and
// this call (internal iter-0 barrier orders A writes vs A reads).
__device__ __forceinline__ void gemm_pipe(
    const uint4* __restrict__ Wf, int nch,
    const unsigned* A32, int sa, uint4* bstage,
    float acc[16][4], int tid, int wm, int wn, int lane)
{
    const int g = lane >> 2, t = lane & 3;
    #pragma unroll
    for (int s = 0; s < NSTG - 1; ++s) {        // nch is always >= NSTG-1
        stage_chunk(bstage + s * 256, Wf + s * 256, tid);
        CP_COMMIT();
    }
    const unsigned* arow0 = A32 + (wm * 32 + g) * sa + t;
    const unsigned* arow1 = arow0 + 16 * sa;
    for (int kk = 0; kk < nch; ++kk) {
        CP_WAIT(NSTG - 2);          // chunk kk complete (always-commit keeps count exact)
        __syncthreads();
        const uint4* bb = bstage + (kk % NSTG) * 256 + wn * 128 + lane;
        const int ka = kk * 8;
        const unsigned a00 = arow0[ka];
        const unsigned a01 = arow0[8 * sa + ka];
        const unsigned a02 = arow0[ka + 4];
        const unsigned a03 = arow0[8 * sa + ka + 4];
        const unsigned a10 = arow1[ka];
        const unsigned a11 = arow1[8 * sa + ka];
        const unsigned a12 = arow1[ka + 4];
        const unsigned a13 = arow1[8 * sa + ka + 4];
        const uint4 f0 = bb[0];
        const uint4 f1 = bb[32];
        const uint4 f2 = bb[64];
        const uint4 f3 = bb[96];
        mma_bf16(acc[0],  a00, a01, a02, a03, f0.x, f0.y);
        mma_bf16(acc[1],  a00, a01, a02, a03, f0.z, f0.w);
        mma_bf16(acc[2],  a00, a01, a02, a03, f1.x, f1.y);
        mma_bf16(acc[3],  a00, a01, a02, a03, f1.z, f1.w);
        mma_bf16(acc[4],  a00, a01, a02, a03, f2.x, f2.y);
        mma_bf16(acc[5],  a00, a01, a02, a03, f2.z, f2.w);
        mma_bf16(acc[6],  a00, a01, a02, a03, f3.x, f3.y);
        mma_bf16(acc[7],  a00, a01, a02, a03, f3.z, f3.w);
        mma_bf16(acc[8],  a10, a11, a12, a13, f0.x, f0.y);
        mma_bf16(acc[9],  a10, a11, a12, a13, f0.z, f0.w);
        mma_bf16(acc[10], a10, a11, a12, a13, f1.x, f1.y);
        mma_bf16(acc[11], a10, a11, a12, a13, f1.z, f1.w);
        mma_bf16(acc[12], a10, a11, a12, a13, f2.x, f2.y);
        mma_bf16(acc[13], a10, a11, a12, a13, f2.z, f2.w);
        mma_bf16(acc[14], a10, a11, a12, a13, f3.x, f3.y);
        mma_bf16(acc[15], a10, a11, a12, a13, f3.z, f3.w);
        const int nk = kk + NSTG - 1;
        if (nk < nch)
            stage_chunk(bstage + (nk % NSTG) * 256, Wf + nk * 256, tid);
        CP_COMMIT();                // empty group when past the end — keeps arithmetic
    }
}

__device__ __forceinline__ void acc_zero(float acc[16][4]) {
    #pragma unroll
    for (int i = 0; i < 16; ++i)
        #pragma unroll
        for (int j = 0; j < 4; ++j) acc[i][j] = 0.f;
}

// epilogue: silu(acc + bias) -> packed bf16x2 smem
__device__ __forceinline__ void epi_silu_bf(
    float acc[16][4], unsigned* Out32, int s32, const float* bias,
    int wm, int wn, int g, int t)
{
    #pragma unroll
    for (int mi = 0; mi < 2; ++mi) {
        const int r0 = wm * 32 + mi * 16 + g;
        #pragma unroll
        for (int n8 = 0; n8 < 8; ++n8) {
            const int c = wn * 64 + n8 * 8 + 2 * t;
            const float b0 = bias[c], b1 = bias[c + 1];
            const float* a = acc[mi * 8 + n8];
            Out32[r0 * s32 + (c >> 1)] =
                pack_bf2(silu_f(a[0] + b0), silu_f(a[1] + b1));
            Out32[(r0 + 8) * s32 + (c >> 1)] =
                pack_bf2(silu_f(a[2] + b0), silu_f(a[3] + b1));
        }
    }
}

// ---------------- fused edge kernel ----------------
__global__ __launch_bounds__(128, 3) void edge_kernel(
    const float* __restrict__ h, const float* __restrict__ x,
    const int* __restrict__ ei, const float* __restrict__ eattr,
    const float* __restrict__ EW1,
    const float* __restrict__ eb1, const float* __restrict__ eb2,
    const float* __restrict__ cb1, const float* __restrict__ CW2,
    const float* __restrict__ AW, const float* __restrict__ ab)
{
    extern __shared__ unsigned dsm[];
    unsigned* A1 = dsm;                      // [64][132] u32
    unsigned* Mm = dsm;                      // [64][68] alias (A1 dead after GEMM1)
    unsigned* M1 = dsm + EM * SA1;           // [64][68]
    unsigned* P  = M1;
    uint4* bstage = (uint4*)(dsm + EM * SA1 + EM * SM1);   // [NSTG][256] uint4

    __shared__ int   s_row[EM];
    __shared__ float s_cd[EM][3];
    __shared__ float s_rad[EM], s_ea[EM], s_att[EM];
    __shared__ float s_b1[HH], s_b2[HH], s_bc[HH], s_aw[HH], s_c2[HH];
    __shared__ float s_wr[HH], s_we[HH];

    const int tid  = threadIdx.x;
    const int lane = tid & 31, warp = tid >> 5;
    const int g = lane >> 2, t = lane & 3;
    const int wm = warp & 1, wn = warp >> 1;
    const int e0 = blockIdx.x * EM;

    if (tid < HH) {
        s_b1[tid] = eb1[tid]; s_b2[tid] = eb2[tid]; s_bc[tid] = cb1[tid];
        s_aw[tid] = AW[tid];  s_c2[tid] = CW2[tid];
        s_wr[tid] = EW1[256 * HH + tid];
        s_we[tid] = EW1[257 * HH + tid];
    }
    if (tid < EM) {
        const int e = tid;
        const int idx = e0 + e;
        const int r = ei[idx], c = ei[EE + idx];
        s_row[e] = r;
        float rad = 0.f;
        #pragma unroll
        for (int d = 0; d < 3; ++d) {
            const float df = x[r * 3 + d] - x[c * 3 + d];
            s_cd[e][d] = df; rad += df * df;
        }
        s_rad[e] = rad;
        s_ea[e] = eattr[idx];
    }
    // gather h[row], h[col], pack bf16x2 (4 warps: e = p*4 + warp)
    #pragma unroll
    for (int p = 0; p < 16; ++p) {
        const int e = p * 4 + warp;
        const int idx = e0 + e;
        const int r = ei[idx], c = ei[EE + idx];
        const float4 vr = *(const float4*)&h[r * HH + lane * 4];
        const float4 vc = *(const float4*)&h[c * HH + lane * 4];
        uint2 ur, uc;
        ur.x = pack_bf2(vr.x, vr.y); ur.y = pack_bf2(vr.z, vr.w);
        uc.x = pack_bf2(vc.x, vc.y); uc.y = pack_bf2(vc.z, vc.w);
        *(uint2*)&A1[e * SA1 + lane * 2]      = ur;
        *(uint2*)&A1[e * SA1 + 64 + lane * 2] = uc;
    }

    float acc[16][4];

    // ---- layer 1: K=256 bf16 + fp32 rank-2 tail ----
    acc_zero(acc);
    gemm_pipe(g_ew1f, 16, A1, SA1, bstage, acc, tid, wm, wn, lane);
    {
        const int r = wm * 32 + g;
        #pragma unroll
        for (int mi = 0; mi < 2; ++mi) {
            const float r0 = s_rad[r + mi * 16], r1 = s_rad[r + mi * 16 + 8];
            const float e0f = s_ea[r + mi * 16], e1f = s_ea[r + mi * 16 + 8];
            #pragma unroll
            for (int n8 = 0; n8 < 8; ++n8) {
                const int c = wn * 64 + n8 * 8 + 2 * t;
                float* a = acc[mi * 8 + n8];
                a[0] += r0 * s_wr[c]     + e0f * s_we[c];
                a[1] += r0 * s_wr[c + 1] + e0f * s_we[c + 1];
                a[2] += r1 * s_wr[c]     + e1f * s_we[c];
                a[3] += r1 * s_wr[c + 1] + e1f * s_we[c + 1];
            }
        }
    }
    epi_silu_bf(acc, M1, SM1, s_b1, wm, wn, g, t);
    __syncthreads();

    // ---- layer 2: K=128 ----
    acc_zero(acc);
    gemm_pipe(g_ew2f, 8, M1, SM1, bstage, acc, tid, wm, wn, lane);
    epi_silu_bf(acc, Mm, SM1, s_b2, wm, wn, g, t);   // Mm aliases dead A1
    __syncthreads();

    // ---- attention gate: 2 threads per edge ----
    {
        const int e = tid >> 1, q = tid & 1;
        const unsigned* mrow = Mm + e * SM1 + q * 32;
        const float* aw = s_aw + q * 64;
        float s = 0.f;
        #pragma unroll
        for (int k = 0; k < 32; ++k) {
            const unsigned u = mrow[k];
            s += bf_lo(u) * aw[2 * k] + bf_hi(u) * aw[2 * k + 1];
        }
        s += __shfl_down_sync(0xffffffffu, s, 1);
        if (q == 0) s_att[e] = sigmoid_f(s + ab[0]);
    }
    __syncthreads();

    // ---- gate + vectorized scatter ----
    #pragma unroll
    for (int p = 0; p < 16; ++p) {
        const int q = p * 128 + tid;
        const int e = q >> 5, j = q & 31;
        unsigned* base = Mm + e * SM1 + 2 * j;
        const float a = s_att[e];
        const unsigned u0 = base[0], u1 = base[1];
        const float f0 = bf_lo(u0) * a, f1 = bf_hi(u0) * a;
        const float f2 = bf_lo(u1) * a, f3 = bf_hi(u1) * a;
        red_add_v4(&g_agg[s_row[e] * HH + 4 * j], f0, f1, f2, f3);
        base[0] = pack_bf2(f0, f1);
        base[1] = pack_bf2(f2, f3);
    }
    __syncthreads();

    // ---- coord MLP layer: K=128 ----
    acc_zero(acc);
    gemm_pipe(g_cw1f, 8, Mm, SM1, bstage, acc, tid, wm, wn, lane);
    epi_silu_bf(acc, P, SM1, s_bc, wm, wn, g, t);    // P aliases dead M1
    __syncthreads();

    // ---- coord_update + fused coord/count scatter ----
    {
        const int e = tid >> 1, q = tid & 1;
        const unsigned* prow = P + e * SM1 + q * 32;
        const float* c2 = s_c2 + q * 64;
        float s = 0.f;
        #pragma unroll
        for (int k = 0; k < 32; ++k) {
            const unsigned u = prow[k];
            s += bf_lo(u) * c2[2 * k] + bf_hi(u) * c2[2 * k + 1];
        }
        s += __shfl_down_sync(0xffffffffu, s, 1);
        if (q == 0) {
            const int r = s_row[e];
            red_add_v4(&g_coordcnt[r * 4],
                       s_cd[e][0] * s, s_cd[e][1] * s, s_cd[e][2] * s, 1.0f);
        }
    }
}

// ---------------- node kernel ----------------
__global__ __launch_bounds__(128, 3) void node_kernel(
    const float* __restrict__ h, const float* __restrict__ x,
    const float* __restrict__ nb1, const float* __restrict__ nb2,
    float* __restrict__ out_h, float* __restrict__ out_x)
{
    extern __shared__ unsigned dsm[];
    unsigned* A1 = dsm;                      // [64][132]
    unsigned* M1 = dsm + EM * SA1;           // [64][68]
    uint4* bstage = (uint4*)(dsm + EM * SA1 + EM * SM1);

    __shared__ float s_nb1[HH], s_nb2[HH];

    const int tid  = threadIdx.x;
    const int lane = tid & 31, warp = tid >> 5;
    const int g = lane >> 2, t = lane & 3;
    const int wm = warp & 1, wn = warp >> 1;
    const int n0 = blockIdx.x * EM;

    if (tid < HH) { s_nb1[tid] = nb1[tid]; s_nb2[tid] = nb2[tid]; }
    #pragma unroll
    for (int p = 0; p < 16; ++p) {
        const int n = p * 4 + warp;
        int r = n0 + n; if (r >= NN) r = NN - 1;
        const float4 vh = *(const float4*)&h[r * HH + lane * 4];
        const float4 va = *(const float4*)&g_agg[r * HH + lane * 4];
        uint2 uh, ua;
        uh.x = pack_bf2(vh.x, vh.y); uh.y = pack_bf2(vh.z, vh.w);
        ua.x = pack_bf2(va.x, va.y); ua.y = pack_bf2(va.z, va.w);
        *(uint2*)&A1[n * SA1 + lane * 2]      = uh;
        *(uint2*)&A1[n * SA1 + 64 + lane * 2] = ua;
    }

    float acc[16][4];
    acc_zero(acc);
    gemm_pipe(g_nw1f, 16, A1, SA1, bstage, acc, tid, wm, wn, lane);
    epi_silu_bf(acc, M1, SM1, s_nb1, wm, wn, g, t);
    __syncthreads();

    acc_zero(acc);
    gemm_pipe(g_nw2f, 8, M1, SM1, bstage, acc, tid, wm, wn, lane);

    // residual epilogue straight to gmem (fp32)
    #pragma unroll
    for (int mi = 0; mi < 2; ++mi) {
        const int r0 = n0 + wm * 32 + mi * 16 + g;
        #pragma unroll
        for (int n8 = 0; n8 < 8; ++n8) {
            const int c = wn * 64 + n8 * 8 + 2 * t;
            const float b0 = s_nb2[c], b1 = s_nb2[c + 1];
            const float* a = acc[mi * 8 + n8];
            if (r0 < NN) {
                float2 v;
                v.x = h[r0 * HH + c]     + a[0] + b0;
                v.y = h[r0 * HH + c + 1] + a[1] + b1;
                *(float2*)&out_h[r0 * HH + c] = v;
            }
            if (r0 + 8 < NN) {
                float2 v;
                v.x = h[(r0 + 8) * HH + c]     + a[2] + b0;
                v.y = h[(r0 + 8) * HH + c + 1] + a[3] + b1;
                *(float2*)&out_h[(r0 + 8) * HH + c] = v;
            }
        }
    }

    for (int i = tid; i < EM * DD; i += 128) {
        const int n = i / 3, d = i % 3;
        const int r = n0 + n;
        if (r < NN) {
            float cnt = g_coordcnt[r * 4 + 3];
            cnt = (cnt < 1.0f) ? 1.0f : cnt;
            out_x[r * 3 + d] = x[r * 3 + d] + g_coordcnt[r * 4 + d] / cnt;
        }
    }
}

// ---------------- launch ----------------
extern "C" void kernel_launch(void* const* d_in, const int* in_sizes, int n_in,
                              void* d_out, int out_size) {
    const float* h     = (const float*)d_in[0];
    const float* x     = (const float*)d_in[1];
    const int*   ei    = (const int*)d_in[2];
    const float* eattr = (const float*)d_in[3];
    const float* EW1   = (const float*)d_in[4];
    const float* eb1   = (const float*)d_in[5];
    const float* EW2   = (const float*)d_in[6];
    const float* eb2   = (const float*)d_in[7];
    const float* NW1   = (const float*)d_in[8];
    const float* nb1   = (const float*)d_in[9];
    const float* NW2   = (const float*)d_in[10];
    const float* nb2   = (const float*)d_in[11];
    const float* CW1   = (const float*)d_in[12];
    const float* cb1   = (const float*)d_in[13];
    const float* CW2   = (const float*)d_in[14];
    const float* AW    = (const float*)d_in[15];
    const float* ab    = (const float*)d_in[16];

    float* out_h = (float*)d_out;
    float* out_x = (float*)d_out + (size_t)NN * HH;

    // A1 + M1 + bstage = (64*132 + 64*68)*4 + 5*4096 = 51,200 + 20,480 = 71,680 B
    const int smem_bytes = (EM * SA1 + EM * SM1) * 4 + NSTG * 4096;
    cudaFuncSetAttribute(edge_kernel,
                         cudaFuncAttributeMaxDynamicSharedMemorySize, smem_bytes);
    cudaFuncSetAttribute(node_kernel,
                         cudaFuncAttributeMaxDynamicSharedMemorySize, smem_bytes);

    zero_kernel<<<1024, 256>>>();
    prep_kernel<<<56, 256>>>(EW1, EW2, CW1, NW1, NW2);
    edge_kernel<<<EE / EM, 128, smem_bytes>>>(h, x, ei, eattr, EW1,
                                              eb1, eb2, cb1, CW2, AW, ab);
    node_kernel<<<(NN + EM - 1) / EM, 128, smem_bytes>>>(h, x, nb1, nb2,
                                                         out_h, out_x);
}

// round 14
// speedup vs baseline: 1.3841x; 1.2635x over previous
#include <cuda_runtime.h>

#define NN 50000
#define EE 800000
#define HH 128
#define DD 3
#define EME 128    // edges per edge-block
#define EMN 64     // nodes per node-block
#define SA1 132    // layer-1 A stride in u32 (bf16x2 pairs)
#define SM1 68     // M buffers stride in u32

// ---------------- device scratch ----------------
__device__ __align__(16) float g_agg[NN * HH];
__device__ __align__(16) float g_coordcnt[NN * 4];   // {cx, cy, cz, cnt}
// fragment-prepacked bf16 weights: [chunk][p=0..7][lane=0..31] uint4
__device__ __align__(16) uint4 g_ew1f[16 * 256];   // K=256
__device__ __align__(16) uint4 g_ew2f[8 * 256];    // K=128
__device__ __align__(16) uint4 g_cw1f[8 * 256];    // K=128
__device__ __align__(16) uint4 g_nw1f[16 * 256];   // K=256
__device__ __align__(16) uint4 g_nw2f[8 * 256];    // K=128

__device__ __forceinline__ float silu_f(float v) { return v / (1.0f + __expf(-v)); }
__device__ __forceinline__ float sigmoid_f(float v) { return 1.0f / (1.0f + __expf(-v)); }

__device__ __forceinline__ unsigned pack_bf2(float lo, float hi) {
    unsigned d; asm("cvt.rn.bf16x2.f32 %0, %1, %2;" : "=r"(d) : "f"(hi), "f"(lo));
    return d;
}
__device__ __forceinline__ float bf_lo(unsigned u) { return __uint_as_float(u << 16); }
__device__ __forceinline__ float bf_hi(unsigned u) { return __uint_as_float(u & 0xffff0000u); }

__device__ __forceinline__ void mma_bf16(float c[4],
    unsigned a0, unsigned a1, unsigned a2, unsigned a3,
    unsigned b0, unsigned b1)
{
    asm volatile("mma.sync.aligned.m16n8k16.row.col.f32.bf16.bf16.f32 "
        "{%0,%1,%2,%3}, {%4,%5,%6,%7}, {%8,%9}, {%0,%1,%2,%3};\n"
        : "+f"(c[0]), "+f"(c[1]), "+f"(c[2]), "+f"(c[3])
        : "r"(a0), "r"(a1), "r"(a2), "r"(a3), "r"(b0), "r"(b1));
}
__device__ __forceinline__ void red_add_v4(float* p, float a, float b, float c, float d) {
    asm volatile("red.global.add.v4.f32 [%0], {%1,%2,%3,%4};"
                 :: "l"(p), "f"(a), "f"(b), "f"(c), "f"(d) : "memory");
}

__global__ void zero_kernel() {
    const int total = NN * HH + NN * 4;
    for (int i = blockIdx.x * blockDim.x + threadIdx.x; i < total;
         i += gridDim.x * blockDim.x) {
        if (i < NN * HH) g_agg[i] = 0.0f;
        else g_coordcnt[i - NN * HH] = 0.0f;
    }
}

// Pack weights into bf16 mma fragment order (layout unchanged from round 8).
__global__ void prep_kernel(const float* __restrict__ EW1, const float* __restrict__ EW2,
                            const float* __restrict__ CW1, const float* __restrict__ NW1,
                            const float* __restrict__ NW2) {
    const int idx = blockIdx.x * blockDim.x + threadIdx.x;
    if (idx >= 56 * 256) return;
    const int chunk = idx >> 8;
    const int rem = idx & 255;
    const int p = rem >> 5, lane = rem & 31;
    const int t = lane & 3, g = lane >> 2;

    const float* W; uint4* dst; int kbase; int loc;
    if (chunk < 16)      { W = EW1; dst = g_ew1f; loc = chunk;      kbase = loc * 16; }
    else if (chunk < 24) { W = EW2; dst = g_ew2f; loc = chunk - 16; kbase = loc * 16; }
    else if (chunk < 32) { W = CW1; dst = g_cw1f; loc = chunk - 24; kbase = loc * 16; }
    else if (chunk < 48) { W = NW1; dst = g_nw1f; loc = chunk - 32; kbase = loc * 16; }
    else                 { W = NW2; dst = g_nw2f; loc = chunk - 48; kbase = loc * 16; }

    const int c0 = p * 16 + g;
    const int c1 = c0 + 8;
    const int k0 = kbase + 2 * t;
    uint4 v;
    v.x = pack_bf2(W[k0 * HH + c0],       W[(k0 + 1) * HH + c0]);
    v.y = pack_bf2(W[(k0 + 8) * HH + c0], W[(k0 + 9) * HH + c0]);
    v.z = pack_bf2(W[k0 * HH + c1],       W[(k0 + 1) * HH + c1]);
    v.w = pack_bf2(W[(k0 + 8) * HH + c1], W[(k0 + 9) * HH + c1]);
    dst[loc * 256 + p * 32 + lane] = v;
}

// bf16 GEMM, 32x64 warp tile (identical per-warp shape to round 8):
// acc[16][4] += A[warp 32 rows, K] @ W[K, warp 64 cols]
// wm selects the 32-row group, wn the 64-col group.
__device__ __forceinline__ void gemm_bf(
    const uint4* __restrict__ Wf, int nchunks,
    const unsigned* A32, int sa,
    float acc[16][4], int wm, int wn, int g, int t, int lane)
{
    const unsigned* arow0 = A32 + (wm * 32 + g) * sa + t;
    const unsigned* arow1 = arow0 + 16 * sa;
    const uint4* wc = Wf + wn * 128 + lane;
    for (int kk = 0; kk < nchunks; ++kk) {
        const int ka = kk * 8;
        const unsigned a00 = arow0[ka];
        const unsigned a01 = arow0[8 * sa + ka];
        const unsigned a02 = arow0[ka + 4];
        const unsigned a03 = arow0[8 * sa + ka + 4];
        const unsigned a10 = arow1[ka];
        const unsigned a11 = arow1[8 * sa + ka];
        const unsigned a12 = arow1[ka + 4];
        const unsigned a13 = arow1[8 * sa + ka + 4];
        const uint4 f0 = wc[kk * 256];
        const uint4 f1 = wc[kk * 256 + 32];
        const uint4 f2 = wc[kk * 256 + 64];
        const uint4 f3 = wc[kk * 256 + 96];
        mma_bf16(acc[0],  a00, a01, a02, a03, f0.x, f0.y);
        mma_bf16(acc[1],  a00, a01, a02, a03, f0.z, f0.w);
        mma_bf16(acc[2],  a00, a01, a02, a03, f1.x, f1.y);
        mma_bf16(acc[3],  a00, a01, a02, a03, f1.z, f1.w);
        mma_bf16(acc[4],  a00, a01, a02, a03, f2.x, f2.y);
        mma_bf16(acc[5],  a00, a01, a02, a03, f2.z, f2.w);
        mma_bf16(acc[6],  a00, a01, a02, a03, f3.x, f3.y);
        mma_bf16(acc[7],  a00, a01, a02, a03, f3.z, f3.w);
        mma_bf16(acc[8],  a10, a11, a12, a13, f0.x, f0.y);
        mma_bf16(acc[9],  a10, a11, a12, a13, f0.z, f0.w);
        mma_bf16(acc[10], a10, a11, a12, a13, f1.x, f1.y);
        mma_bf16(acc[11], a10, a11, a12, a13, f1.z, f1.w);
        mma_bf16(acc[12], a10, a11, a12, a13, f2.x, f2.y);
        mma_bf16(acc[13], a10, a11, a12, a13, f2.z, f2.w);
        mma_bf16(acc[14], a10, a11, a12, a13, f3.x, f3.y);
        mma_bf16(acc[15], a10, a11, a12, a13, f3.z, f3.w);
    }
}

__device__ __forceinline__ void acc_zero(float acc[16][4]) {
    #pragma unroll
    for (int i = 0; i < 16; ++i)
        #pragma unroll
        for (int j = 0; j < 4; ++j) acc[i][j] = 0.f;
}

// epilogue: silu(acc + bias) -> packed bf16x2 smem
__device__ __forceinline__ void epi_silu_bf(
    float acc[16][4], unsigned* Out32, int s32, const float* bias,
    int wm, int wn, int g, int t)
{
    #pragma unroll
    for (int mi = 0; mi < 2; ++mi) {
        const int r0 = wm * 32 + mi * 16 + g;
        #pragma unroll
        for (int n8 = 0; n8 < 8; ++n8) {
            const int c = wn * 64 + n8 * 8 + 2 * t;
            const float b0 = bias[c], b1 = bias[c + 1];
            const float* a = acc[mi * 8 + n8];
            Out32[r0 * s32 + (c >> 1)] =
                pack_bf2(silu_f(a[0] + b0), silu_f(a[1] + b1));
            Out32[(r0 + 8) * s32 + (c >> 1)] =
                pack_bf2(silu_f(a[2] + b0), silu_f(a[3] + b1));
        }
    }
}

// ---------------- fused edge kernel: 256 threads, 128 edges/block ----------------
__global__ __launch_bounds__(256, 2) void edge_kernel(
    const float* __restrict__ h, const float* __restrict__ x,
    const int* __restrict__ ei, const float* __restrict__ eattr,
    const float* __restrict__ EW1,
    const float* __restrict__ eb1, const float* __restrict__ eb2,
    const float* __restrict__ cb1, const float* __restrict__ CW2,
    const float* __restrict__ AW, const float* __restrict__ ab)
{
    extern __shared__ unsigned dsm[];
    unsigned* A1 = dsm;                      // [128][132] u32
    unsigned* Mm = dsm;                      // [128][68] alias (A1 dead after GEMM1)
    unsigned* M1 = dsm + EME * SA1;          // [128][68]
    unsigned* P  = M1;

    __shared__ int   s_row[EME];
    __shared__ float s_cd[EME][3];
    __shared__ float s_rad[EME], s_ea[EME], s_att[EME];
    __shared__ float s_b1[HH], s_b2[HH], s_bc[HH], s_aw[HH], s_c2[HH];
    __shared__ float s_wr[HH], s_we[HH];

    const int tid  = threadIdx.x;
    const int lane = tid & 31, warp = tid >> 5;
    const int g = lane >> 2, t = lane & 3;
    const int wm = warp & 3, wn = warp >> 2;     // 4 M-groups x 2 N-groups
    const int e0 = blockIdx.x * EME;

    if (tid < HH) {
        s_b1[tid] = eb1[tid]; s_b2[tid] = eb2[tid]; s_bc[tid] = cb1[tid];
        s_aw[tid] = AW[tid];  s_c2[tid] = CW2[tid];
        s_wr[tid] = EW1[256 * HH + tid];
        s_we[tid] = EW1[257 * HH + tid];
    }
    if (tid >= 128) {     // geometry on second half: edges 0..127
        const int e = tid - 128;
        const int idx = e0 + e;
        const int r = ei[idx], c = ei[EE + idx];
        s_row[e] = r;
        float rad = 0.f;
        #pragma unroll
        for (int d = 0; d < 3; ++d) {
            const float df = x[r * 3 + d] - x[c * 3 + d];
            s_cd[e][d] = df; rad += df * df;
        }
        s_rad[e] = rad;
        s_ea[e] = eattr[idx];
    }
    // gather h[row], h[col], pack bf16x2 (8 warps: e = p*8 + warp)
    #pragma unroll
    for (int p = 0; p < 16; ++p) {
        const int e = p * 8 + warp;
        const int idx = e0 + e;
        const int r = ei[idx], c = ei[EE + idx];
        const float4 vr = *(const float4*)&h[r * HH + lane * 4];
        const float4 vc = *(const float4*)&h[c * HH + lane * 4];
        uint2 ur, uc;
        ur.x = pack_bf2(vr.x, vr.y); ur.y = pack_bf2(vr.z, vr.w);
        uc.x = pack_bf2(vc.x, vc.y); uc.y = pack_bf2(vc.z, vc.w);
        *(uint2*)&A1[e * SA1 + lane * 2]      = ur;
        *(uint2*)&A1[e * SA1 + 64 + lane * 2] = uc;
    }
    __syncthreads();

    float acc[16][4];

    // ---- layer 1: K=256 bf16 + fp32 rank-2 tail ----
    acc_zero(acc);
    gemm_bf(g_ew1f, 16, A1, SA1, acc, wm, wn, g, t, lane);
    {
        const int r = wm * 32 + g;
        #pragma unroll
        for (int mi = 0; mi < 2; ++mi) {
            const float r0 = s_rad[r + mi * 16], r1 = s_rad[r + mi * 16 + 8];
            const float e0f = s_ea[r + mi * 16], e1f = s_ea[r + mi * 16 + 8];
            #pragma unroll
            for (int n8 = 0; n8 < 8; ++n8) {
                const int c = wn * 64 + n8 * 8 + 2 * t;
                float* a = acc[mi * 8 + n8];
                a[0] += r0 * s_wr[c]     + e0f * s_we[c];
                a[1] += r0 * s_wr[c + 1] + e0f * s_we[c + 1];
                a[2] += r1 * s_wr[c]     + e1f * s_we[c];
                a[3] += r1 * s_wr[c + 1] + e1f * s_we[c + 1];
            }
        }
    }
    epi_silu_bf(acc, M1, SM1, s_b1, wm, wn, g, t);
    __syncthreads();

    // ---- layer 2: K=128 ----
    acc_zero(acc);
    gemm_bf(g_ew2f, 8, M1, SM1, acc, wm, wn, g, t, lane);
    epi_silu_bf(acc, Mm, SM1, s_b2, wm, wn, g, t);   // Mm aliases dead A1
    __syncthreads();

    // ---- attention gate: 2 threads per edge (256 thr / 128 edges) ----
    {
        const int e = tid >> 1, q = tid & 1;
        const unsigned* mrow = Mm + e * SM1 + q * 32;
        const float* aw = s_aw + q * 64;
        float s = 0.f;
        #pragma unroll
        for (int k = 0; k < 32; ++k) {
            const unsigned u = mrow[k];
            s += bf_lo(u) * aw[2 * k] + bf_hi(u) * aw[2 * k + 1];
        }
        s += __shfl_down_sync(0xffffffffu, s, 1);
        if (q == 0) s_att[e] = sigmoid_f(s + ab[0]);
    }
    __syncthreads();

    // ---- gate + vectorized scatter: 128 edges x 32 groups / 256 thr ----
    #pragma unroll
    for (int p = 0; p < 16; ++p) {
        const int q = p * 256 + tid;
        const int e = q >> 5, j = q & 31;
        unsigned* base = Mm + e * SM1 + 2 * j;
        const float a = s_att[e];
        const unsigned u0 = base[0], u1 = base[1];
        const float f0 = bf_lo(u0) * a, f1 = bf_hi(u0) * a;
        const float f2 = bf_lo(u1) * a, f3 = bf_hi(u1) * a;
        red_add_v4(&g_agg[s_row[e] * HH + 4 * j], f0, f1, f2, f3);
        base[0] = pack_bf2(f0, f1);
        base[1] = pack_bf2(f2, f3);
    }
    __syncthreads();

    // ---- coord MLP layer: K=128 ----
    acc_zero(acc);
    gemm_bf(g_cw1f, 8, Mm, SM1, acc, wm, wn, g, t, lane);
    epi_silu_bf(acc, P, SM1, s_bc, wm, wn, g, t);    // P aliases dead M1
    __syncthreads();

    // ---- coord_update + fused coord/count scatter ----
    {
        const int e = tid >> 1, q = tid & 1;
        const unsigned* prow = P + e * SM1 + q * 32;
        const float* c2 = s_c2 + q * 64;
        float s = 0.f;
        #pragma unroll
        for (int k = 0; k < 32; ++k) {
            const unsigned u = prow[k];
            s += bf_lo(u) * c2[2 * k] + bf_hi(u) * c2[2 * k + 1];
        }
        s += __shfl_down_sync(0xffffffffu, s, 1);
        if (q == 0) {
            const int r = s_row[e];
            red_add_v4(&g_coordcnt[r * 4],
                       s_cd[e][0] * s, s_cd[e][1] * s, s_cd[e][2] * s, 1.0f);
        }
    }
}

// ---------------- node kernel (unchanged round-8 winner) ----------------
__global__ __launch_bounds__(128, 4) void node_kernel(
    const float* __restrict__ h, const float* __restrict__ x,
    const float* __restrict__ nb1, const float* __restrict__ nb2,
    float* __restrict__ out_h, float* __restrict__ out_x)
{
    extern __shared__ unsigned dsm[];
    unsigned* A1 = dsm;                 // [64][132]
    unsigned* M1 = dsm + EMN * SA1;     // [64][68]

    __shared__ float s_nb1[HH], s_nb2[HH];

    const int tid  = threadIdx.x;
    const int lane = tid & 31, warp = tid >> 5;
    const int g = lane >> 2, t = lane & 3;
    const int wm = warp & 1, wn = warp >> 1;
    const int n0 = blockIdx.x * EMN;

    if (tid < HH) { s_nb1[tid] = nb1[tid]; s_nb2[tid] = nb2[tid]; }
    #pragma unroll
    for (int p = 0; p < 16; ++p) {
        const int n = p * 4 + warp;
        int r = n0 + n; if (r >= NN) r = NN - 1;
        const float4 vh = *(const float4*)&h[r * HH + lane * 4];
        const float4 va = *(const float4*)&g_agg[r * HH + lane * 4];
        uint2 uh, ua;
        uh.x = pack_bf2(vh.x, vh.y); uh.y = pack_bf2(vh.z, vh.w);
        ua.x = pack_bf2(va.x, va.y); ua.y = pack_bf2(va.z, va.w);
        *(uint2*)&A1[n * SA1 + lane * 2]      = uh;
        *(uint2*)&A1[n * SA1 + 64 + lane * 2] = ua;
    }
    __syncthreads();

    float acc[16][4];
    acc_zero(acc);
    gemm_bf(g_nw1f, 16, A1, SA1, acc, wm, wn, g, t, lane);
    epi_silu_bf(acc, M1, SM1, s_nb1, wm, wn, g, t);
    __syncthreads();

    acc_zero(acc);
    gemm_bf(g_nw2f, 8, M1, SM1, acc, wm, wn, g, t, lane);

    // residual epilogue straight to gmem (fp32)
    #pragma unroll
    for (int mi = 0; mi < 2; ++mi) {
        const int r0 = n0 + wm * 32 + mi * 16 + g;
        #pragma unroll
        for (int n8 = 0; n8 < 8; ++n8) {
            const int c = wn * 64 + n8 * 8 + 2 * t;
            const float b0 = s_nb2[c], b1 = s_nb2[c + 1];
            const float* a = acc[mi * 8 + n8];
            if (r0 < NN) {
                float2 v;
                v.x = h[r0 * HH + c]     + a[0] + b0;
                v.y = h[r0 * HH + c + 1] + a[1] + b1;
                *(float2*)&out_h[r0 * HH + c] = v;
            }
            if (r0 + 8 < NN) {
                float2 v;
                v.x = h[(r0 + 8) * HH + c]     + a[2] + b0;
                v.y = h[(r0 + 8) * HH + c + 1] + a[3] + b1;
                *(float2*)&out_h[(r0 + 8) * HH + c] = v;
            }
        }
    }

    for (int i = tid; i < EMN * DD; i += 128) {
        const int n = i / 3, d = i % 3;
        const int r = n0 + n;
        if (r < NN) {
            float cnt = g_coordcnt[r * 4 + 3];
            cnt = (cnt < 1.0f) ? 1.0f : cnt;
            out_x[r * 3 + d] = x[r * 3 + d] + g_coordcnt[r * 4 + d] / cnt;
        }
    }
}

// ---------------- launch ----------------
extern "C" void kernel_launch(void* const* d_in, const int* in_sizes, int n_in,
                              void* d_out, int out_size) {
    const float* h     = (const float*)d_in[0];
    const float* x     = (const float*)d_in[1];
    const int*   ei    = (const int*)d_in[2];
    const float* eattr = (const float*)d_in[3];
    const float* EW1   = (const float*)d_in[4];
    const float* eb1   = (const float*)d_in[5];
    const float* EW2   = (const float*)d_in[6];
    const float* eb2   = (const float*)d_in[7];
    const float* NW1   = (const float*)d_in[8];
    const float* nb1   = (const float*)d_in[9];
    const float* NW2   = (const float*)d_in[10];
    const float* nb2   = (const float*)d_in[11];
    const float* CW1   = (const float*)d_in[12];
    const float* cb1   = (const float*)d_in[13];
    const float* CW2   = (const float*)d_in[14];
    const float* AW    = (const float*)d_in[15];
    const float* ab    = (const float*)d_in[16];

    float* out_h = (float*)d_out;
    float* out_x = (float*)d_out + (size_t)NN * HH;

    const int smem_edge = (EME * SA1 + EME * SM1) * 4;   // 102,400 B
    const int smem_node = (EMN * SA1 + EMN * SM1) * 4;   //  51,200 B
    cudaFuncSetAttribute(edge_kernel,
                         cudaFuncAttributeMaxDynamicSharedMemorySize, smem_edge);
    cudaFuncSetAttribute(node_kernel,
                         cudaFuncAttributeMaxDynamicSharedMemorySize, smem_node);

    zero_kernel<<<1024, 256>>>();
    prep_kernel<<<56, 256>>>(EW1, EW2, CW1, NW1, NW2);
    edge_kernel<<<EE / EME, 256, smem_edge>>>(h, x, ei, eattr, EW1,
                                              eb1, eb2, cb1, CW2, AW, ab);
    node_kernel<<<(NN + EMN - 1) / EMN, 128, smem_node>>>(h, x, nb1, nb2,
                                                          out_h, out_x);
}

// round 17
// speedup vs baseline: 1.6699x; 1.2065x over previous
#include <cuda_runtime.h>
#include <cuda_fp16.h>
#include <cstdint>

#define NN 50000
#define EE 800000
#define HH 128
#define EM 64      // edges (or nodes) per block
#define SA1 132    // node-kernel layer-1 A stride in u32 (K=256)
#define SM1 68     // 128-wide fp16x2 buffer stride in u32

// ---------------- device scratch ----------------
__device__ __align__(16) float g_agg[NN * HH];
__device__ __align__(16) float g_coordcnt[NN * 4];   // {cx, cy, cz, cnt}
// per-node projections, packed fp16x2: row n = [P_r (64 u32) | P_c (64 u32)]
__device__ __align__(16) unsigned g_proj[NN * 128];
// fragment-prepacked fp16 weights (R8 fragment layout)
__device__ __align__(16) uint4 g_w1af[8 * 256];    // e_w1 rows 0..127
__device__ __align__(16) uint4 g_w1bf[8 * 256];    // e_w1 rows 128..255
__device__ __align__(16) uint4 g_w2f[8 * 256];     // e_w2
__device__ __align__(16) uint4 g_w3f[8 * 256];     // c_w1
__device__ __align__(16) uint4 g_nw1f[16 * 256];   // n_w1 (K=256)
__device__ __align__(16) uint4 g_nw2f[8 * 256];    // n_w2

__device__ __forceinline__ float silu_f(float v) { return v / (1.0f + __expf(-v)); }
__device__ __forceinline__ float sigmoid_f(float v) { return 1.0f / (1.0f + __expf(-v)); }

// pack two fp32 -> f16x2 (lo in low half; first PTX src -> high half)
__device__ __forceinline__ unsigned pack_h2(float lo, float hi) {
    unsigned d; asm("cvt.rn.f16x2.f32 %0, %1, %2;" : "=r"(d) : "f"(hi), "f"(lo));
    return d;
}
__device__ __forceinline__ float h2lo(unsigned u) {
    return __half2float(__ushort_as_half((unsigned short)(u & 0xffffu)));
}
__device__ __forceinline__ float h2hi(unsigned u) {
    return __half2float(__ushort_as_half((unsigned short)(u >> 16)));
}
__device__ __forceinline__ void mma_f16(float c[4],
    unsigned a0, unsigned a1, unsigned a2, unsigned a3, unsigned b0, unsigned b1)
{
    asm volatile("mma.sync.aligned.m16n8k16.row.col.f32.f16.f16.f32 "
        "{%0,%1,%2,%3}, {%4,%5,%6,%7}, {%8,%9}, {%0,%1,%2,%3};\n"
        : "+f"(c[0]), "+f"(c[1]), "+f"(c[2]), "+f"(c[3])
        : "r"(a0), "r"(a1), "r"(a2), "r"(a3), "r"(b0), "r"(b1));
}
__device__ __forceinline__ void red_add_v4(float* p, float a, float b, float c, float d) {
    asm volatile("red.global.add.v4.f32 [%0], {%1,%2,%3,%4};"
                 :: "l"(p), "f"(a), "f"(b), "f"(c), "f"(d) : "memory");
}

__global__ void zero_kernel() {
    const int total = NN * HH + NN * 4;
    for (int i = blockIdx.x * blockDim.x + threadIdx.x; i < total;
         i += gridDim.x * blockDim.x) {
        if (i < NN * HH) g_agg[i] = 0.0f;
        else g_coordcnt[i - NN * HH] = 0.0f;
    }
}

// Pack all weight matrices into f16 mma fragment order (R8 layout).
__global__ void prep_w(const float* __restrict__ EW1, const float* __restrict__ EW2,
                       const float* __restrict__ CW1, const float* __restrict__ NW1,
                       const float* __restrict__ NW2) {
    const int idx = blockIdx.x * blockDim.x + threadIdx.x;
    if (idx >= 56 * 256) return;
    const int chunk = idx >> 8, rem = idx & 255;
    const int p = rem >> 5, lane = rem & 31;
    const int t = lane & 3, g = lane >> 2;

    const float* W; uint4* dst; int loc;
    if (chunk < 8)       { W = EW1;            dst = g_w1af; loc = chunk; }
    else if (chunk < 16) { W = EW1 + 128 * HH; dst = g_w1bf; loc = chunk - 8; }
    else if (chunk < 24) { W = EW2;            dst = g_w2f;  loc = chunk - 16; }
    else if (chunk < 32) { W = CW1;            dst = g_w3f;  loc = chunk - 24; }
    else if (chunk < 48) { W = NW1;            dst = g_nw1f; loc = chunk - 32; }
    else                 { W = NW2;            dst = g_nw2f; loc = chunk - 48; }

    const int kbase = loc * 16;
    const int c0 = p * 16 + g, c1 = c0 + 8;
    const int k0 = kbase + 2 * t;
    uint4 v;
    v.x = pack_h2(W[k0 * HH + c0],       W[(k0 + 1) * HH + c0]);
    v.y = pack_h2(W[(k0 + 8) * HH + c0], W[(k0 + 9) * HH + c0]);
    v.z = pack_h2(W[k0 * HH + c1],       W[(k0 + 1) * HH + c1]);
    v.w = pack_h2(W[(k0 + 8) * HH + c1], W[(k0 + 9) * HH + c1]);
    dst[loc * 256 + p * 32 + lane] = v;
}

// fp16 GEMM, 32x64 warp tile (R8 shape): acc[16][4] += A[warp 32 rows, K] @ W[K, warp 64 cols]
__device__ __forceinline__ void gemm_h(
    const uint4* __restrict__ Wf, int nchunks,
    const unsigned* A32, int sa,
    float acc[16][4], int wm, int wn, int g, int t, int lane)
{
    const unsigned* arow0 = A32 + (wm * 32 + g) * sa + t;
    const unsigned* arow1 = arow0 + 16 * sa;
    const uint4* wc = Wf + wn * 128 + lane;
    for (int kk = 0; kk < nchunks; ++kk) {
        const int ka = kk * 8;
        const unsigned a00 = arow0[ka];
        const unsigned a01 = arow0[8 * sa + ka];
        const unsigned a02 = arow0[ka + 4];
        const unsigned a03 = arow0[8 * sa + ka + 4];
        const unsigned a10 = arow1[ka];
        const unsigned a11 = arow1[8 * sa + ka];
        const unsigned a12 = arow1[ka + 4];
        const unsigned a13 = arow1[8 * sa + ka + 4];
        const uint4 f0 = wc[kk * 256];
        const uint4 f1 = wc[kk * 256 + 32];
        const uint4 f2 = wc[kk * 256 + 64];
        const uint4 f3 = wc[kk * 256 + 96];
        mma_f16(acc[0],  a00, a01, a02, a03, f0.x, f0.y);
        mma_f16(acc[1],  a00, a01, a02, a03, f0.z, f0.w);
        mma_f16(acc[2],  a00, a01, a02, a03, f1.x, f1.y);
        mma_f16(acc[3],  a00, a01, a02, a03, f1.z, f1.w);
        mma_f16(acc[4],  a00, a01, a02, a03, f2.x, f2.y);
        mma_f16(acc[5],  a00, a01, a02, a03, f2.z, f2.w);
        mma_f16(acc[6],  a00, a01, a02, a03, f3.x, f3.y);
        mma_f16(acc[7],  a00, a01, a02, a03, f3.z, f3.w);
        mma_f16(acc[8],  a10, a11, a12, a13, f0.x, f0.y);
        mma_f16(acc[9],  a10, a11, a12, a13, f0.z, f0.w);
        mma_f16(acc[10], a10, a11, a12, a13, f1.x, f1.y);
        mma_f16(acc[11], a10, a11, a12, a13, f1.z, f1.w);
        mma_f16(acc[12], a10, a11, a12, a13, f2.x, f2.y);
        mma_f16(acc[13], a10, a11, a12, a13, f2.z, f2.w);
        mma_f16(acc[14], a10, a11, a12, a13, f3.x, f3.y);
        mma_f16(acc[15], a10, a11, a12, a13, f3.z, f3.w);
    }
}

__device__ __forceinline__ void acc_zero(float acc[16][4]) {
    #pragma unroll
    for (int i = 0; i < 16; ++i)
        #pragma unroll
        for (int j = 0; j < 4; ++j) acc[i][j] = 0.f;
}

// epilogue: silu(acc + bias) -> packed f16x2 smem
__device__ __forceinline__ void epi_silu_h(
    float acc[16][4], unsigned* Out32, int s32, const float* bias,
    int wm, int wn, int g, int t)
{
    #pragma unroll
    for (int mi = 0; mi < 2; ++mi) {
        const int r0 = wm * 32 + mi * 16 + g;
        #pragma unroll
        for (int n8 = 0; n8 < 8; ++n8) {
            const int c = wn * 64 + n8 * 8 + 2 * t;
            const float b0 = bias[c], b1 = bias[c + 1];
            const float* a = acc[mi * 8 + n8];
            Out32[r0 * s32 + (c >> 1)] =
                pack_h2(silu_f(a[0] + b0), silu_f(a[1] + b1));
            Out32[(r0 + 8) * s32 + (c >> 1)] =
                pack_h2(silu_f(a[2] + b0), silu_f(a[3] + b1));
        }
    }
}

// ---------------- node projection kernel: P_r = h@W1a, P_c = h@W1b ----------------
__global__ __launch_bounds__(128, 4) void proj_kernel(const float* __restrict__ h) {
    extern __shared__ unsigned dsm[];
    unsigned* A1 = dsm;                 // [64][68] packed fp16 h

    const int tid  = threadIdx.x;
    const int lane = tid & 31, warp = tid >> 5;
    const int g = lane >> 2, t = lane & 3;
    const int wm = warp & 1, wn = warp >> 1;
    const int n0 = blockIdx.x * EM;

    #pragma unroll
    for (int p = 0; p < 16; ++p) {
        const int n = p * 4 + warp;
        int r = n0 + n; if (r >= NN) r = NN - 1;
        const float4 vh = *(const float4*)&h[r * HH + lane * 4];
        uint2 uh;
        uh.x = pack_h2(vh.x, vh.y); uh.y = pack_h2(vh.z, vh.w);
        *(uint2*)&A1[n * SM1 + lane * 2] = uh;
    }
    __syncthreads();

    float acc[16][4];
    // P_r
    acc_zero(acc);
    gemm_h(g_w1af, 8, A1, SM1, acc, wm, wn, g, t, lane);
    #pragma unroll
    for (int mi = 0; mi < 2; ++mi) {
        const int r0 = n0 + wm * 32 + mi * 16 + g;
        #pragma unroll
        for (int n8 = 0; n8 < 8; ++n8) {
            const int c = wn * 64 + n8 * 8 + 2 * t;
            const float* a = acc[mi * 8 + n8];
            if (r0 < NN)     g_proj[r0 * 128 + (c >> 1)]       = pack_h2(a[0], a[1]);
            if (r0 + 8 < NN) g_proj[(r0 + 8) * 128 + (c >> 1)] = pack_h2(a[2], a[3]);
        }
    }
    // P_c
    acc_zero(acc);
    gemm_h(g_w1bf, 8, A1, SM1, acc, wm, wn, g, t, lane);
    #pragma unroll
    for (int mi = 0; mi < 2; ++mi) {
        const int r0 = n0 + wm * 32 + mi * 16 + g;
        #pragma unroll
        for (int n8 = 0; n8 < 8; ++n8) {
            const int c = wn * 64 + n8 * 8 + 2 * t;
            const float* a = acc[mi * 8 + n8];
            if (r0 < NN)     g_proj[r0 * 128 + 64 + (c >> 1)]       = pack_h2(a[0], a[1]);
            if (r0 + 8 < NN) g_proj[(r0 + 8) * 128 + 64 + (c >> 1)] = pack_h2(a[2], a[3]);
        }
    }
}

// ---------------- fused edge kernel (layer-1 via projection gather) ----------------
__global__ __launch_bounds__(128, 4) void edge_kernel(
    const float* __restrict__ x,
    const int* __restrict__ ei, const float* __restrict__ eattr,
    const float* __restrict__ EW1,
    const float* __restrict__ eb1, const float* __restrict__ eb2,
    const float* __restrict__ cb1, const float* __restrict__ CW2,
    const float* __restrict__ AW, const float* __restrict__ ab)
{
    extern __shared__ unsigned dsm[];
    unsigned* M1 = dsm;                 // [64][68]  layer1 out; later P
    unsigned* Mm = dsm + EM * SM1;      // [64][68]  gated messages
    unsigned* P  = M1;

    __shared__ int   s_row[EM];
    __shared__ float s_cd[EM][3];
    __shared__ float s_rad[EM], s_ea[EM], s_att[EM];
    __shared__ float s_b1[HH], s_b2[HH], s_bc[HH], s_aw[HH], s_c2[HH];
    __shared__ float s_wr[HH], s_we[HH];

    const int tid  = threadIdx.x;
    const int lane = tid & 31, warp = tid >> 5;
    const int g = lane >> 2, t = lane & 3;
    const int wm = warp & 1, wn = warp >> 1;
    const int e0 = blockIdx.x * EM;

    if (tid < HH) {
        s_b1[tid] = eb1[tid]; s_b2[tid] = eb2[tid]; s_bc[tid] = cb1[tid];
        s_aw[tid] = AW[tid];  s_c2[tid] = CW2[tid];
        s_wr[tid] = EW1[256 * HH + tid];
        s_we[tid] = EW1[257 * HH + tid];
    }
    if (tid < EM) {
        const int e = tid;
        const int idx = e0 + e;
        const int r = ei[idx], c = ei[EE + idx];
        s_row[e] = r;
        float rad = 0.f;
        #pragma unroll
        for (int d = 0; d < 3; ++d) {
            const float df = x[r * 3 + d] - x[c * 3 + d];
            s_cd[e][d] = df; rad += df * df;
        }
        s_rad[e] = rad;
        s_ea[e] = eattr[idx];
    }
    __syncthreads();

    // ---- layer 1: gather P_r[row], P_c[col]; add tail; silu -> M1 ----
    #pragma unroll
    for (int p = 0; p < 16; ++p) {
        const int e = p * 4 + warp;
        const int idx = e0 + e;
        const int r = ei[idx], c = ei[EE + idx];
        const uint2 upr = *(const uint2*)&g_proj[r * 128 + lane * 2];
        const uint2 upc = *(const uint2*)&g_proj[c * 128 + 64 + lane * 2];
        const int c0 = lane * 4;
        const float rad = s_rad[e], eav = s_ea[e];
        const float f0 = h2lo(upr.x) + h2lo(upc.x) + rad * s_wr[c0]     + eav * s_we[c0]     + s_b1[c0];
        const float f1 = h2hi(upr.x) + h2hi(upc.x) + rad * s_wr[c0 + 1] + eav * s_we[c0 + 1] + s_b1[c0 + 1];
        const float f2 = h2lo(upr.y) + h2lo(upc.y) + rad * s_wr[c0 + 2] + eav * s_we[c0 + 2] + s_b1[c0 + 2];
        const float f3 = h2hi(upr.y) + h2hi(upc.y) + rad * s_wr[c0 + 3] + eav * s_we[c0 + 3] + s_b1[c0 + 3];
        uint2 o;
        o.x = pack_h2(silu_f(f0), silu_f(f1));
        o.y = pack_h2(silu_f(f2), silu_f(f3));
        *(uint2*)&M1[e * SM1 + lane * 2] = o;
    }
    __syncthreads();

    float acc[16][4];

    // ---- layer 2: K=128 ----
    acc_zero(acc);
    gemm_h(g_w2f, 8, M1, SM1, acc, wm, wn, g, t, lane);
    epi_silu_h(acc, Mm, SM1, s_b2, wm, wn, g, t);
    __syncthreads();

    // ---- attention gate: 2 threads per edge ----
    {
        const int e = tid >> 1, q = tid & 1;
        const unsigned* mrow = Mm + e * SM1 + q * 32;
        const float* aw = s_aw + q * 64;
        float s = 0.f;
        #pragma unroll
        for (int k = 0; k < 32; ++k) {
            const unsigned u = mrow[k];
            s += h2lo(u) * aw[2 * k] + h2hi(u) * aw[2 * k + 1];
        }
        s += __shfl_down_sync(0xffffffffu, s, 1);
        if (q == 0) s_att[e] = sigmoid_f(s + ab[0]);
    }
    __syncthreads();

    // ---- gate + vectorized scatter ----
    #pragma unroll
    for (int p = 0; p < 16; ++p) {
        const int q = p * 128 + tid;
        const int e = q >> 5, j = q & 31;
        unsigned* base = Mm + e * SM1 + 2 * j;
        const float a = s_att[e];
        const unsigned u0 = base[0], u1 = base[1];
        const float f0 = h2lo(u0) * a, f1 = h2hi(u0) * a;
        const float f2 = h2lo(u1) * a, f3 = h2hi(u1) * a;
        red_add_v4(&g_agg[s_row[e] * HH + 4 * j], f0, f1, f2, f3);
        base[0] = pack_h2(f0, f1);
        base[1] = pack_h2(f2, f3);
    }
    __syncthreads();

    // ---- coord MLP layer: K=128 ----
    acc_zero(acc);
    gemm_h(g_w3f, 8, Mm, SM1, acc, wm, wn, g, t, lane);
    epi_silu_h(acc, P, SM1, s_bc, wm, wn, g, t);    // P aliases dead M1
    __syncthreads();

    // ---- coord_update + fused coord/count scatter ----
    {
        const int e = tid >> 1, q = tid & 1;
        const unsigned* prow = P + e * SM1 + q * 32;
        const float* c2 = s_c2 + q * 64;
        float s = 0.f;
        #pragma unroll
        for (int k = 0; k < 32; ++k) {
            const unsigned u = prow[k];
            s += h2lo(u) * c2[2 * k] + h2hi(u) * c2[2 * k + 1];
        }
        s += __shfl_down_sync(0xffffffffu, s, 1);
        if (q == 0) {
            const int r = s_row[e];
            red_add_v4(&g_coordcnt[r * 4],
                       s_cd[e][0] * s, s_cd[e][1] * s, s_cd[e][2] * s, 1.0f);
        }
    }
}

// ---------------- node kernel (R8 winner, fp16) ----------------
__global__ __launch_bounds__(128, 4) void node_kernel(
    const float* __restrict__ h, const float* __restrict__ x,
    const float* __restrict__ nb1, const float* __restrict__ nb2,
    float* __restrict__ out_h, float* __restrict__ out_x)
{
    extern __shared__ unsigned dsm[];
    unsigned* A1 = dsm;                 // [64][132]
    unsigned* M1 = dsm + EM * SA1;      // [64][68]

    __shared__ float s_nb1[HH], s_nb2[HH];

    const int tid  = threadIdx.x;
    const int lane = tid & 31, warp = tid >> 5;
    const int g = lane >> 2, t = lane & 3;
    const int wm = warp & 1, wn = warp >> 1;
    const int n0 = blockIdx.x * EM;

    if (tid < HH) { s_nb1[tid] = nb1[tid]; s_nb2[tid] = nb2[tid]; }
    #pragma unroll
    for (int p = 0; p < 16; ++p) {
        const int n = p * 4 + warp;
        int r = n0 + n; if (r >= NN) r = NN - 1;
        const float4 vh = *(const float4*)&h[r * HH + lane * 4];
        const float4 va = *(const float4*)&g_agg[r * HH + lane * 4];
        uint2 uh, ua;
        uh.x = pack_h2(vh.x, vh.y); uh.y = pack_h2(vh.z, vh.w);
        ua.x = pack_h2(va.x, va.y); ua.y = pack_h2(va.z, va.w);
        *(uint2*)&A1[n * SA1 + lane * 2]      = uh;
        *(uint2*)&A1[n * SA1 + 64 + lane * 2] = ua;
    }
    __syncthreads();

    float acc[16][4];
    acc_zero(acc);
    gemm_h(g_nw1f, 16, A1, SA1, acc, wm, wn, g, t, lane);
    epi_silu_h(acc, M1, SM1, s_nb1, wm, wn, g, t);
    __syncthreads();

    acc_zero(acc);
    gemm_h(g_nw2f, 8, M1, SM1, acc, wm, wn, g, t, lane);

    // residual epilogue straight to gmem (fp32)
    #pragma unroll
    for (int mi = 0; mi < 2; ++mi) {
        const int r0 = n0 + wm * 32 + mi * 16 + g;
        #pragma unroll
        for (int n8 = 0; n8 < 8; ++n8) {
            const int c = wn * 64 + n8 * 8 + 2 * t;
            const float b0 = s_nb2[c], b1 = s_nb2[c + 1];
            const float* a = acc[mi * 8 + n8];
            if (r0 < NN) {
                float2 v;
                v.x = h[r0 * HH + c]     + a[0] + b0;
                v.y = h[r0 * HH + c + 1] + a[1] + b1;
                *(float2*)&out_h[r0 * HH + c] = v;
            }
            if (r0 + 8 < NN) {
                float2 v;
                v.x = h[(r0 + 8) * HH + c]     + a[2] + b0;
                v.y = h[(r0 + 8) * HH + c + 1] + a[3] + b1;
                *(float2*)&out_h[(r0 + 8) * HH + c] = v;
            }
        }
    }

    for (int i = tid; i < EM * 3; i += 128) {
        const int n = i / 3, d = i % 3;
        const int r = n0 + n;
        if (r < NN) {
            float cnt = g_coordcnt[r * 4 + 3];
            cnt = (cnt < 1.0f) ? 1.0f : cnt;
            out_x[r * 3 + d] = x[r * 3 + d] + g_coordcnt[r * 4 + d] / cnt;
        }
    }
}

// ---------------- launch ----------------
extern "C" void kernel_launch(void* const* d_in, const int* in_sizes, int n_in,
                              void* d_out, int out_size) {
    const float* h     = (const float*)d_in[0];
    const float* x     = (const float*)d_in[1];
    const int*   ei    = (const int*)d_in[2];
    const float* eattr = (const float*)d_in[3];
    const float* EW1   = (const float*)d_in[4];
    const float* eb1   = (const float*)d_in[5];
    const float* EW2   = (const float*)d_in[6];
    const float* eb2   = (const float*)d_in[7];
    const float* NW1   = (const float*)d_in[8];
    const float* nb1   = (const float*)d_in[9];
    const float* NW2   = (const float*)d_in[10];
    const float* nb2   = (const float*)d_in[11];
    const float* CW1   = (const float*)d_in[12];
    const float* cb1   = (const float*)d_in[13];
    const float* CW2   = (const float*)d_in[14];
    const float* AW    = (const float*)d_in[15];
    const float* ab    = (const float*)d_in[16];

    float* out_h = (float*)d_out;
    float* out_x = (float*)d_out + (size_t)NN * HH;

    const int smem_proj = EM * SM1 * 4;               // 17,408 B
    const int smem_edge = 2 * EM * SM1 * 4;           // 34,816 B
    const int smem_node = (EM * SA1 + EM * SM1) * 4;  // 51,200 B
    cudaFuncSetAttribute(proj_kernel,
                         cudaFuncAttributeMaxDynamicSharedMemorySize, smem_proj);
    cudaFuncSetAttribute(edge_kernel,
                         cudaFuncAttributeMaxDynamicSharedMemorySize, smem_edge);
    cudaFuncSetAttribute(node_kernel,
                         cudaFuncAttributeMaxDynamicSharedMemorySize, smem_node);

    zero_kernel<<<1024, 256>>>();
    prep_w<<<56, 256>>>(EW1, EW2, CW1, NW1, NW2);
    proj_kernel<<<(NN + EM - 1) / EM, 128, smem_proj>>>(h);
    edge_kernel<<<EE / EM, 128, smem_edge>>>(x, ei, eattr, EW1,
                                             eb1, eb2, cb1, CW2, AW, ab);
    node_kernel<<<(NN + EM - 1) / EM, 128, smem_node>>>(h, x, nb1, nb2,
                                                        out_h, out_x);
}